// round 12
// baseline (speedup 1.0000x reference)
#include <cuda_runtime.h>

// AvgSeq: out[b,s,d] = cumsum_s(x[b,s,d]) / (s+1)
// 3-pass chunked scan, fully float4-vectorized. B=16, S=8192, D=256, fp32.

#define B 16
#define S 8192
#define D 256
#define DV (D / 4)       // 64 float4 lanes per row
#define NC 128           // seq chunks
#define CLEN (S / NC)    // 64 seq steps per chunk

// Per-(b, chunk, d) partial sums: 16*128*256 floats = 2 MB (L2-resident).
__device__ float g_partial[B * NC * D];

// Pass 1: thread = one float4 lane; sums its chunk (64 x LDG.128).
// Reverse chunk order so low addresses are L2-freshest for pass3.
__global__ void __launch_bounds__(DV) pass1_chunk_sums(const float4* __restrict__ x) {
    const int t = threadIdx.x;
    const int c = (NC - 1) - blockIdx.x;   // reverse order
    const int b = blockIdx.y;
    const float4* p = x + ((size_t)b * S + (size_t)c * CLEN) * DV + t;
    float4 sum = make_float4(0.f, 0.f, 0.f, 0.f);
#pragma unroll 8
    for (int s = 0; s < CLEN; ++s) {
        const float4 v = p[(size_t)s * DV];
        sum.x += v.x; sum.y += v.y; sum.z += v.z; sum.w += v.w;
    }
    ((float4*)g_partial)[(b * NC + c) * DV + t] = sum;
}

// Pass 2: exclusive scan over NC chunk sums per (b, d) column.
// Scalar, serial over c; 2 MB array is L2-hot from pass1. Off critical path.
__global__ void __launch_bounds__(D) pass2_scan_sums() {
    const int d = threadIdx.x;
    const int b = blockIdx.x;
    float run = 0.f;
#pragma unroll 8
    for (int c = 0; c < NC; ++c) {
        const int idx = (b * NC + c) * D + d;
        const float t = g_partial[idx];
        g_partial[idx] = run;   // exclusive prefix
        run += t;
    }
}

// Pass 3: re-read input, local scan + offset, scale by shared-memory
// reciprocal table, evict-first float4 stores.
__global__ void __launch_bounds__(DV) pass3_scan_out(const float4* __restrict__ x,
                                                     float4* __restrict__ y) {
    __shared__ float s_recip[CLEN];
    const int t = threadIdx.x;
    const int c = blockIdx.x;
    const int b = blockIdx.y;
    const int s0 = c * CLEN;

    // Exactly one reciprocal per thread (DV == CLEN == 64).
    s_recip[t] = __fdividef(1.0f, (float)(s0 + t + 1));
    __syncthreads();

    float4 run = ((const float4*)g_partial)[(b * NC + c) * DV + t];
    const size_t base = ((size_t)b * S + (size_t)c * CLEN) * DV + t;
    const float4* p = x + base;
    float4* q = y + base;
#pragma unroll 8
    for (int s = 0; s < CLEN; ++s) {
        const float4 v = p[(size_t)s * DV];
        run.x += v.x; run.y += v.y; run.z += v.z; run.w += v.w;
        const float r = s_recip[s];
        float4 o;
        o.x = run.x * r; o.y = run.y * r; o.z = run.z * r; o.w = run.w * r;
        __stcs(q + (size_t)s * DV, o);
    }
}

extern "C" void kernel_launch(void* const* d_in, const int* in_sizes, int n_in,
                              void* d_out, int out_size) {
    const float4* x = (const float4*)d_in[0];
    float4* y = (float4*)d_out;

    dim3 grid(NC, B);
    pass1_chunk_sums<<<grid, DV>>>(x);
    pass2_scan_sums<<<B, D>>>();
    pass3_scan_out<<<grid, DV>>>(x, y);
}